// round 2
// baseline (speedup 1.0000x reference)
#include <cuda_runtime.h>
#include <math.h>

#define HID 256
#define QN 64
#define LQ 20
#define DN 24
#define LD 50
#define QROWS (QN*LQ)   // 1280
#define DROWS (DN*LD)   // 1200

// ---------------- scratch (device globals; no allocation allowed) ----------
__device__ __align__(16) float g_xq[QROWS*HID];
__device__ __align__(16) float g_xd[DROWS*HID];
__device__ __align__(16) float g_giq[QROWS*768];
__device__ __align__(16) float g_gic[DROWS*768];
__device__ __align__(16) float g_gia[DROWS*768];
__device__ __align__(16) float g_hq[2][QN*HID];
__device__ __align__(16) float g_hc[2][DN*HID];
__device__ __align__(16) float g_ha[2][DN*HID];
__device__ __align__(16) float g_cfin[DN*HID];
__device__ unsigned g_bar[3*64];

// ---------------- K0: embedding gather -------------------------------------
__global__ void gather_k(const int* __restrict__ qt, const int* __restrict__ pt,
                         const int* __restrict__ nt,
                         const float* __restrict__ temb, const float* __restrict__ demb) {
    int row = blockIdx.x;
    const float4* src; float4* dst;
    if (row < QROWS) {
        src = (const float4*)(temb + (size_t)qt[row]*HID);
        dst = (float4*)(g_xq + (size_t)row*HID);
    } else {
        int r = row - QROWS;
        int tok = (r < 600) ? pt[r] : nt[r-600];
        src = (const float4*)(demb + (size_t)tok*HID);
        dst = (float4*)(g_xd + (size_t)r*HID);
    }
    dst[threadIdx.x] = src[threadIdx.x];   // 64 threads x float4 = 256 floats
}

// ---------------- K1: gi = X @ W^T + b (three segments) --------------------
#define BM 64
#define BN 64
#define BK 32

__global__ void __launch_bounds__(256) gi_gemm_k(
    const float* __restrict__ tW, const float* __restrict__ tb,
    const float* __restrict__ cW, const float* __restrict__ cb,
    const float* __restrict__ aW, const float* __restrict__ ab) {
    const int NT = 768/BN;          // 12
    const int mt0 = QROWS/BM;       // 20
    const int mt1 = (DROWS+BM-1)/BM;// 19
    int bid = blockIdx.x;
    const float* X; const float* W; const float* bias; float* C; int M; int mtile;
    if (bid < mt0*NT)               { X=g_xq; W=tW; bias=tb; C=g_giq; M=QROWS; mtile=bid/NT; }
    else if (bid < (mt0+mt1)*NT)    { int b=bid-mt0*NT;        X=g_xd; W=cW; bias=cb; C=g_gic; M=DROWS; mtile=b/NT; }
    else                            { int b=bid-(mt0+mt1)*NT;  X=g_xd; W=aW; bias=ab; C=g_gia; M=DROWS; mtile=b/NT; }
    int ntile = bid % NT;
    int m0 = mtile*BM, n0 = ntile*BN;

    __shared__ float As[BK][BM+4];
    __shared__ float Bs[BK][BN+4];
    int tid = threadIdx.x;
    int tx = tid & 15, ty = tid >> 4;
    float acc[4][4] = {};

    for (int k0 = 0; k0 < HID; k0 += BK) {
        #pragma unroll
        for (int i = 0; i < 2; i++) {
            int idx = tid*2 + i;          // 0..511
            int m  = idx >> 3;
            int kk = (idx & 7) << 2;
            float4 v = make_float4(0.f,0.f,0.f,0.f);
            if (m0+m < M) v = *(const float4*)(X + (size_t)(m0+m)*HID + k0 + kk);
            As[kk+0][m]=v.x; As[kk+1][m]=v.y; As[kk+2][m]=v.z; As[kk+3][m]=v.w;
        }
        #pragma unroll
        for (int i = 0; i < 2; i++) {
            int idx = tid*2 + i;
            int n  = idx >> 3;
            int kk = (idx & 7) << 2;
            float4 v = *(const float4*)(W + (size_t)(n0+n)*HID + k0 + kk);
            Bs[kk+0][n]=v.x; Bs[kk+1][n]=v.y; Bs[kk+2][n]=v.z; Bs[kk+3][n]=v.w;
        }
        __syncthreads();
        #pragma unroll
        for (int k = 0; k < BK; k++) {
            float a[4], b[4];
            #pragma unroll
            for (int i=0;i<4;i++) a[i] = As[k][ty*4+i];
            #pragma unroll
            for (int j=0;j<4;j++) b[j] = Bs[k][tx*4+j];
            #pragma unroll
            for (int i=0;i<4;i++)
                #pragma unroll
                for (int j=0;j<4;j++) acc[i][j] = fmaf(a[i], b[j], acc[i][j]);
        }
        __syncthreads();
    }
    #pragma unroll
    for (int i=0;i<4;i++) {
        int m = m0 + ty*4 + i;
        if (m >= M) continue;
        int n = n0 + tx*4;
        float4 o;
        o.x = acc[i][0] + bias[n+0];
        o.y = acc[i][1] + bias[n+1];
        o.z = acc[i][2] + bias[n+2];
        o.w = acc[i][3] + bias[n+3];
        *(float4*)(C + (size_t)m*768 + n) = o;
    }
}

// ---------------- K2: three concurrent GRU scans with per-step barriers ----
#define NC_C 54
#define NC_A 54
#define NC_Q 40
#define SCAN_THREADS 384

__device__ __forceinline__ void bar_arrive_wait(unsigned* p, unsigned need) {
    asm volatile("red.release.gpu.global.add.u32 [%0], %1;" :: "l"(p), "r"(1u) : "memory");
    unsigned v;
    do {
        asm volatile("ld.acquire.gpu.global.u32 %0, [%1];" : "=r"(v) : "l"(p) : "memory");
    } while (v < need);
}

__global__ void __launch_bounds__(SCAN_THREADS) scan_k(
    const float* __restrict__ tWhh, const float* __restrict__ tbhh,
    const float* __restrict__ cWhh, const float* __restrict__ cbhh,
    const float* __restrict__ aWhh, const float* __restrict__ abhh) {
    extern __shared__ float sm[];
    int bid = blockIdx.x;
    int local, NC, B, T, KS;
    const float* Whh; const float* bhh; const float* gi;
    float* hbuf0; float* hbuf1; unsigned* bar;
    if (bid < NC_C) {
        local=bid; NC=NC_C; B=DN; T=LD; KS=4;
        Whh=cWhh; bhh=cbhh; gi=g_gic; hbuf0=g_hc[0]; hbuf1=g_hc[1]; bar=g_bar;
    } else if (bid < NC_C+NC_A) {
        local=bid-NC_C; NC=NC_A; B=DN; T=LD; KS=4;
        Whh=aWhh; bhh=abhh; gi=g_gia; hbuf0=g_ha[0]; hbuf1=g_ha[1]; bar=g_bar+64;
    } else {
        local=bid-NC_C-NC_A; NC=NC_Q; B=QN; T=LQ; KS=1;
        Whh=tWhh; bhh=tbhh; gi=g_giq; hbuf0=g_hq[0]; hbuf1=g_hq[1]; bar=g_bar+128;
    }
    int c0 = local*256/NC, c1 = (local+1)*256/NC;
    int HC = c1 - c0, G = 3*HC;
    int tid = threadIdx.x;

    float* h_s  = sm;              // B*256
    float* W_s  = sm + B*256;      // G*256
    float* part = W_s + G*256;     // B*G*KS

    // stage the Whh slice (rows for our gate columns) into smem once
    for (int idx = tid; idx < G*64; idx += SCAN_THREADS) {
        int g = idx >> 6, kk = (idx & 63) << 2;
        int grow = (g/HC)*256 + c0 + (g - (g/HC)*HC);
        *(float4*)(W_s + g*256 + kk) = *(const float4*)(Whh + (size_t)grow*HID + kk);
    }
    // h0 = 0
    for (int idx = tid; idx < B*64; idx += SCAN_THREADS)
        ((float4*)h_s)[idx] = make_float4(0.f,0.f,0.f,0.f);
    __syncthreads();

    int Btiles = B/2;
    int Gtiles = (G+1)/2;
    int L = 256/KS;
    int nthr = Btiles*Gtiles*KS;
    bool active = tid < nthr;
    int ks=0, b0=0, g0=0; bool g1v=false;
    if (active) {
        ks = tid % KS; int t2 = tid / KS;
        g0 = (t2 % Gtiles)*2; b0 = (t2 / Gtiles)*2;
        g1v = (g0+1 < G);
    }
    int kbeg = ks*L;

    for (int t = 0; t < T; t++) {
        if (active) {
            float a00=0.f,a01=0.f,a10=0.f,a11=0.f;
            const float4* h0p = (const float4*)(h_s + b0*256 + kbeg);
            const float4* h1p = (const float4*)(h_s + (b0+1)*256 + kbeg);
            const float4* w0p = (const float4*)(W_s + g0*256 + kbeg);
            const float4* w1p = (const float4*)(W_s + (g1v? g0+1 : g0)*256 + kbeg);
            #pragma unroll 8
            for (int kk = 0; kk < L/4; kk++) {
                float4 h0 = h0p[kk], h1 = h1p[kk], w0 = w0p[kk], w1 = w1p[kk];
                a00 = fmaf(h0.x,w0.x,a00); a00 = fmaf(h0.y,w0.y,a00);
                a00 = fmaf(h0.z,w0.z,a00); a00 = fmaf(h0.w,w0.w,a00);
                a01 = fmaf(h0.x,w1.x,a01); a01 = fmaf(h0.y,w1.y,a01);
                a01 = fmaf(h0.z,w1.z,a01); a01 = fmaf(h0.w,w1.w,a01);
                a10 = fmaf(h1.x,w0.x,a10); a10 = fmaf(h1.y,w0.y,a10);
                a10 = fmaf(h1.z,w0.z,a10); a10 = fmaf(h1.w,w0.w,a10);
                a11 = fmaf(h1.x,w1.x,a11); a11 = fmaf(h1.y,w1.y,a11);
                a11 = fmaf(h1.z,w1.z,a11); a11 = fmaf(h1.w,w1.w,a11);
            }
            part[(b0*G + g0)*KS + ks] = a00;
            part[((b0+1)*G + g0)*KS + ks] = a10;
            if (g1v) {
                part[(b0*G + g0+1)*KS + ks] = a01;
                part[((b0+1)*G + g0+1)*KS + ks] = a11;
            }
        }
        __syncthreads();
        // reduce over K-splits, gate math, write h_next to global
        float* hdst = ((t+1)&1) ? hbuf1 : hbuf0;
        for (int idx = tid; idx < B*HC; idx += SCAN_THREADS) {
            int b = idx / HC, j = idx - (idx/HC)*HC;
            int c = c0 + j;
            float ghr = bhh[c], ghz = bhh[256+c], ghn = bhh[512+c];
            #pragma unroll
            for (int s = 0; s < 4; s++) {
                if (s < KS) {
                    ghr += part[(b*G + j)*KS + s];
                    ghz += part[(b*G + HC+j)*KS + s];
                    ghn += part[(b*G + 2*HC+j)*KS + s];
                }
            }
            const float* gip = gi + ((size_t)b*T + t)*768;
            float r = 1.f/(1.f + expf(-(gip[c]     + ghr)));
            float z = 1.f/(1.f + expf(-(gip[256+c] + ghz)));
            float n = tanhf(gip[512+c] + r*ghn);
            hdst[b*256 + c] = (1.f - z)*n + z*h_s[b*256 + c];
        }
        __threadfence();
        __syncthreads();
        if (tid == 0) bar_arrive_wait(bar + t, (unsigned)NC);
        __syncthreads();
        if (t+1 < T) {
            const float* hsrc = ((t+1)&1) ? hbuf1 : hbuf0;
            for (int idx = tid; idx < B*64; idx += SCAN_THREADS)
                ((float4*)h_s)[idx] = ((const float4*)hsrc)[idx];
            __syncthreads();
        }
    }
}

// ---------------- K3a: position dense on content vectors -------------------
__global__ void posdense_k(const float* __restrict__ posW, const float* __restrict__ posb,
                           const float* __restrict__ ptab) {
    __shared__ float hs[256];
    __shared__ float pe[4];
    int d = blockIdx.x, j = threadIdx.x;
    hs[j] = g_hc[0][d*256 + j];
    if (j < 4) pe[j] = ptab[(d%12)*4 + j];
    __syncthreads();
    const float* wr = posW + (size_t)j*260;
    float acc = posb[j];
    #pragma unroll 8
    for (int k = 0; k < 256; k += 4) {
        float4 w = *(const float4*)(wr + k);
        acc = fmaf(hs[k],   w.x, acc);
        acc = fmaf(hs[k+1], w.y, acc);
        acc = fmaf(hs[k+2], w.z, acc);
        acc = fmaf(hs[k+3], w.w, acc);
    }
    float4 wp = *(const float4*)(wr + 256);
    acc = fmaf(pe[0],wp.x, fmaf(pe[1],wp.y, fmaf(pe[2],wp.z, fmaf(pe[3],wp.w, acc))));
    g_cfin[d*256 + j] = acc;
}

// ---------------- K3b: attention + final GRU step (h0 = 0) -----------------
__global__ void final_k(const float* __restrict__ qWih, const float* __restrict__ qbih,
                        const float* __restrict__ qbhh, float* __restrict__ out) {
    __shared__ float enc[256];
    __shared__ float wgt[24];
    __shared__ float qpn[256];
    __shared__ float gi2[768];
    int q = blockIdx.x, tid = threadIdx.x;
    enc[tid] = g_hq[0][q*256 + tid];
    __syncthreads();
    if (tid < 24) {
        const float* ar = g_ha[0] + tid*256;
        float s = 0.f;
        #pragma unroll 8
        for (int k = 0; k < 256; k += 4) {
            float4 a = *(const float4*)(ar + k);
            s = fmaf(enc[k],a.x,s); s = fmaf(enc[k+1],a.y,s);
            s = fmaf(enc[k+2],a.z,s); s = fmaf(enc[k+3],a.w,s);
        }
        wgt[tid] = s;
    }
    __syncthreads();
    if (tid < 2) {
        int off = tid*12;
        float mx = -1e30f;
        for (int d=0; d<12; d++) mx = fmaxf(mx, wgt[off+d]);
        float sum = 0.f;
        for (int d=0; d<12; d++) { float e = expf(wgt[off+d]-mx); wgt[off+d]=e; sum += e; }
        float inv = 1.f/sum;
        for (int d=0; d<12; d++) wgt[off+d] *= inv;
    }
    __syncthreads();
    float v = enc[tid];
    #pragma unroll
    for (int d=0; d<24; d++) v = fmaf(wgt[d], g_cfin[d*256 + tid], v);
    qpn[tid] = v;
    __syncthreads();
    for (int g = tid; g < 768; g += 256) {
        const float* wr = qWih + (size_t)g*256;
        float acc = qbih[g];
        #pragma unroll 8
        for (int k = 0; k < 256; k += 4) {
            float4 w = *(const float4*)(wr + k);
            acc = fmaf(qpn[k],w.x,acc); acc = fmaf(qpn[k+1],w.y,acc);
            acc = fmaf(qpn[k+2],w.z,acc); acc = fmaf(qpn[k+3],w.w,acc);
        }
        gi2[g] = acc;
    }
    __syncthreads();
    float r = 1.f/(1.f + expf(-(gi2[tid]     + qbhh[tid])));
    float z = 1.f/(1.f + expf(-(gi2[256+tid] + qbhh[256+tid])));
    float n = tanhf(gi2[512+tid] + r*qbhh[512+tid]);
    out[q*256 + tid] = (1.f - z)*n;
}

// ---------------- launch ----------------------------------------------------
extern "C" void kernel_launch(void* const* d_in, const int* in_sizes, int n_in,
                              void* d_out, int out_size) {
    const int*   qt   = (const int*)d_in[0];
    const int*   pt   = (const int*)d_in[1];
    const int*   nt   = (const int*)d_in[2];
    const float* temb = (const float*)d_in[3];
    const float* tWih = (const float*)d_in[4];
    const float* tWhh = (const float*)d_in[5];
    const float* tbih = (const float*)d_in[6];
    const float* tbhh = (const float*)d_in[7];
    const float* demb = (const float*)d_in[8];
    const float* cWih = (const float*)d_in[9];
    const float* cWhh = (const float*)d_in[10];
    const float* cbih = (const float*)d_in[11];
    const float* cbhh = (const float*)d_in[12];
    const float* aWih = (const float*)d_in[13];
    const float* aWhh = (const float*)d_in[14];
    const float* abih = (const float*)d_in[15];
    const float* abhh = (const float*)d_in[16];
    const float* ptab = (const float*)d_in[17];
    const float* posW = (const float*)d_in[18];
    const float* posb = (const float*)d_in[19];
    const float* qWih = (const float*)d_in[20];
    const float* qbih = (const float*)d_in[22];
    const float* qbhh = (const float*)d_in[23];

    // zero per-step barrier counters (memset node in the graph each replay)
    void* barp = nullptr;
    cudaGetSymbolAddress(&barp, g_bar);
    cudaMemsetAsync(barp, 0, sizeof(unsigned)*3*64);

    gather_k<<<QROWS + DROWS, 64>>>(qt, pt, nt, temb, demb);

    const int NT = 768/BN;
    int nblk = (QROWS/BM)*NT + 2*((DROWS+BM-1)/BM)*NT;   // 240 + 456 = 696
    gi_gemm_k<<<nblk, 256>>>(tWih, tbih, cWih, cbih, aWih, abih);

    // scan smem: max over chains of (B*256 + G*256 + B*G*KS)*4 bytes
    // q-chain: (64*256 + 21*256 + 64*21)*4 = 92416
    int scan_smem = 92416;
    cudaFuncSetAttribute(scan_k, cudaFuncAttributeMaxDynamicSharedMemorySize, scan_smem);
    scan_k<<<NC_C + NC_A + NC_Q, SCAN_THREADS, scan_smem>>>(tWhh, tbhh, cWhh, cbhh, aWhh, abhh);

    posdense_k<<<DN, 256>>>(posW, posb, ptab);
    final_k<<<QN, 256>>>(qWih, qbih, qbhh, (float*)d_out);
}

// round 3
// speedup vs baseline: 2.1536x; 2.1536x over previous
#include <cuda_runtime.h>
#include <math.h>

#define HID 256
#define QN 64
#define LQ 20
#define DN 24
#define LD 50
#define QROWS (QN*LQ)   // 1280
#define DROWS (DN*LD)   // 1200

// ---------------- scratch ----------------------------------------------------
__device__ __align__(16) float g_giq[QROWS*768];
__device__ __align__(16) float g_gic[DROWS*768];
__device__ __align__(16) float g_gia[DROWS*768];
__device__ __align__(16) float g_hq[2][QN*HID];
__device__ __align__(16) float g_hc[2][DN*HID];
__device__ __align__(16) float g_ha[2][DN*HID];
__device__ __align__(16) float g_cfin[DN*HID];
__device__ __align__(16) float g_qpn[QN*HID];
__device__ __align__(16) float g_gi2[QN*768];
__device__ unsigned g_bar[512];

__device__ __forceinline__ float dot4(float4 a, float4 b, float s) {
    s = fmaf(a.x, b.x, s); s = fmaf(a.y, b.y, s);
    s = fmaf(a.z, b.z, s); s = fmaf(a.w, b.w, s);
    return s;
}

// ---------------- K1: gi = emb[tok] @ W^T + b, gather fused ------------------
#define BM 128
#define BN 64
#define BK 32

__global__ void __launch_bounds__(256) gi_gemm_k(
    const int* __restrict__ qt, const int* __restrict__ pt, const int* __restrict__ nt,
    const float* __restrict__ temb, const float* __restrict__ demb,
    const float* __restrict__ tW, const float* __restrict__ tb,
    const float* __restrict__ cW, const float* __restrict__ cb,
    const float* __restrict__ aW, const float* __restrict__ ab) {
    int bid = blockIdx.x;
    int mt = bid / 12, ntile = bid % 12;
    int seg, mtile;
    const float* W; const float* bias; float* C; const float* emb; int M;
    if (mt < 10)      { seg=0; mtile=mt;    W=tW; bias=tb; C=g_giq; emb=temb; M=QROWS; }
    else if (mt < 20) { seg=1; mtile=mt-10; W=cW; bias=cb; C=g_gic; emb=demb; M=DROWS; }
    else              { seg=2; mtile=mt-20; W=aW; bias=ab; C=g_gia; emb=demb; M=DROWS; }
    int m0 = mtile*BM, n0 = ntile*BN;

    __shared__ float As[BK][BM+4];
    __shared__ float Bs[BK][BN+4];
    __shared__ int toks[BM];
    int tid = threadIdx.x;
    if (tid < BM) {
        int m = m0 + tid;
        int tk = 0;
        if (m < M) {
            if (seg == 0) tk = qt[m];
            else tk = (m < 600) ? pt[m] : nt[m-600];
        }
        toks[tid] = tk;
    }
    __syncthreads();
    int tx = tid & 15, ty = tid >> 4;
    float acc[8][4] = {};

    for (int k0 = 0; k0 < HID; k0 += BK) {
        #pragma unroll
        for (int i = 0; i < 4; i++) {
            int idx = tid + i*256;          // 0..1023
            int m  = idx >> 3;
            int kk = (idx & 7) << 2;
            float4 v = make_float4(0.f,0.f,0.f,0.f);
            if (m0+m < M) v = *(const float4*)(emb + (size_t)toks[m]*HID + k0 + kk);
            As[kk+0][m]=v.x; As[kk+1][m]=v.y; As[kk+2][m]=v.z; As[kk+3][m]=v.w;
        }
        #pragma unroll
        for (int i = 0; i < 2; i++) {
            int idx = tid + i*256;          // 0..511
            int n  = idx >> 3;
            int kk = (idx & 7) << 2;
            float4 v = *(const float4*)(W + (size_t)(n0+n)*HID + k0 + kk);
            Bs[kk+0][n]=v.x; Bs[kk+1][n]=v.y; Bs[kk+2][n]=v.z; Bs[kk+3][n]=v.w;
        }
        __syncthreads();
        #pragma unroll
        for (int k = 0; k < BK; k++) {
            float a[8], b[4];
            #pragma unroll
            for (int i=0;i<8;i++) a[i] = As[k][ty*8+i];
            #pragma unroll
            for (int j=0;j<4;j++) b[j] = Bs[k][tx*4+j];
            #pragma unroll
            for (int i=0;i<8;i++)
                #pragma unroll
                for (int j=0;j<4;j++) acc[i][j] = fmaf(a[i], b[j], acc[i][j]);
        }
        __syncthreads();
    }
    #pragma unroll
    for (int i=0;i<8;i++) {
        int m = m0 + ty*8 + i;
        if (m >= M) continue;
        int n = n0 + tx*4;
        float4 o;
        o.x = acc[i][0] + bias[n+0];
        o.y = acc[i][1] + bias[n+1];
        o.z = acc[i][2] + bias[n+2];
        o.w = acc[i][3] + bias[n+3];
        *(float4*)(C + (size_t)m*768 + n) = o;
    }
}

// ---------------- K2: GRU scans, W in registers ------------------------------
// doc CTAs 0..95:  bg=bid/16 (6 groups, 4 docs each), cg=bid%16 (C=16). chains c+a fused.
// qry CTAs 96..127: bg=(bid-96)/8 (4 groups, 16 queries each), cg%8 (C=32).
// Both: 96 gate-rows/CTA, 512 threads, 16 warps x 2 half-warps x 3 rows.
#define DOC_CTAS 96
#define Q_CTAS 32

__device__ __forceinline__ void bar_arrive_wait(unsigned* p, unsigned need) {
    asm volatile("red.release.gpu.global.add.u32 [%0], %1;" :: "l"(p), "r"(1u) : "memory");
    unsigned v;
    do {
        asm volatile("ld.acquire.gpu.global.u32 %0, [%1];" : "=r"(v) : "l"(p) : "memory");
    } while (v < need);
}

__global__ void __launch_bounds__(512) scan_k(
    const float* __restrict__ tWhh, const float* __restrict__ tbhh,
    const float* __restrict__ cWhh, const float* __restrict__ cbhh,
    const float* __restrict__ aWhh, const float* __restrict__ abhh) {
    __shared__ float h_s[16*256];      // doc uses 8 rows (2 chains x 4 b), qry 16 rows
    __shared__ float parts[96*16];     // [row][b], stride 16

    int bid = blockIdx.x, tid = threadIdx.x;
    bool isQ = (bid >= DOC_CTAS);
    int lane = tid & 31, ks = lane & 15;
    int R0r = (tid >> 5)*6 + ((lane >> 4))*3;     // first of my 3 gate rows

    int B, T, c0, bg;
    unsigned* bar; unsigned need;
    if (!isQ) { bg = bid >> 4; c0 = (bid & 15) << 4; B = 4;  T = LD; bar = g_bar + bg*64; need = 16; }
    else { int qb = bid - DOC_CTAS; bg = qb >> 3; c0 = (qb & 7) << 5; B = 16; T = LQ; bar = g_bar + 384 + bg*20; need = 8; }

    // ---- W rows into registers ------------------------------------------------
    float4 w[3][4];
    #pragma unroll
    for (int j = 0; j < 3; j++) {
        int row = R0r + j;
        const float* Wp; int grow;
        if (!isQ) {
            int ch = row / 48; int rr = row - ch*48;
            grow = (rr >> 4)*256 + c0 + (rr & 15);
            Wp = ch ? aWhh : cWhh;
        } else {
            grow = (row >> 5)*256 + c0 + (row & 31);
            Wp = tWhh;
        }
        const float4* wr = (const float4*)(Wp + (size_t)grow*HID) + ks*4;
        w[j][0]=wr[0]; w[j][1]=wr[1]; w[j][2]=wr[2]; w[j][3]=wr[3];
    }
    int hbase = (!isQ) ? (R0r/48)*4 : 0;   // smem h row base for my chain

    // ---- phase-2 per-thread setup --------------------------------------------
    bool oact; int prI=0, pzI=0, pnI=0, hpI=0, hoff=0, cc=0;
    float br=0.f, bz=0.f, bn=0.f;
    const float* giBase = nullptr; float* hd0 = nullptr; float* hd1 = nullptr;
    if (!isQ) {
        oact = (tid < 128);
        if (oact) {
            int chain = tid >> 6, b = (tid >> 4) & 3, cl = tid & 15;
            cc = c0 + cl;
            prI = (chain*48 + cl)*16 + b; pzI = prI + 256; pnI = prI + 512;
            hpI = (chain*4 + b)*256 + cc;
            const float* bh = chain ? abhh : cbhh;
            br = bh[cc]; bz = bh[256+cc]; bn = bh[512+cc];
            giBase = (chain ? g_gia : g_gic) + (size_t)(bg*4 + b)*LD*768;
            hoff = (bg*4 + b)*256 + cc;
            hd0 = chain ? g_ha[0] : g_hc[0];
            hd1 = chain ? g_ha[1] : g_hc[1];
        }
    } else {
        oact = true;
        int b = tid >> 5, cl = tid & 31;
        cc = c0 + cl;
        prI = cl*16 + b; pzI = prI + 512; pnI = prI + 1024;
        hpI = b*256 + cc;
        br = tbhh[cc]; bz = tbhh[256+cc]; bn = tbhh[512+cc];
        giBase = g_giq + (size_t)(bg*16 + b)*LQ*768;
        hoff = (bg*16 + b)*256 + cc;
        hd0 = g_hq[0]; hd1 = g_hq[1];
    }

    // ---- zero h ---------------------------------------------------------------
    #pragma unroll
    for (int i = 0; i < 2; i++)
        ((float4*)h_s)[tid + i*512] = make_float4(0.f,0.f,0.f,0.f);
    __syncthreads();

    for (int t = 0; t < T; t++) {
        // prefetch this step's gi (hides L2 latency under phase-1 FMAs)
        float xr=0.f, xz=0.f, xn=0.f;
        if (oact) {
            const float* gp = giBase + (size_t)t*768;
            xr = gp[cc]; xz = gp[256+cc]; xn = gp[512+cc];
        }
        // phase 1: gh partials, W in regs, h broadcast from smem
        #pragma unroll 4
        for (int b = 0; b < B; b++) {
            const float4* hp = (const float4*)(h_s + (hbase + b)*256) + ks*4;
            float4 a0 = hp[0], a1 = hp[1], a2 = hp[2], a3 = hp[3];
            float s0=0.f, s1=0.f, s2=0.f;
            s0 = dot4(a0,w[0][0],s0); s0 = dot4(a1,w[0][1],s0);
            s0 = dot4(a2,w[0][2],s0); s0 = dot4(a3,w[0][3],s0);
            s1 = dot4(a0,w[1][0],s1); s1 = dot4(a1,w[1][1],s1);
            s1 = dot4(a2,w[1][2],s1); s1 = dot4(a3,w[1][3],s1);
            s2 = dot4(a0,w[2][0],s2); s2 = dot4(a1,w[2][1],s2);
            s2 = dot4(a2,w[2][2],s2); s2 = dot4(a3,w[2][3],s2);
            #pragma unroll
            for (int m = 1; m < 16; m <<= 1) {
                s0 += __shfl_xor_sync(0xffffffffu, s0, m);
                s1 += __shfl_xor_sync(0xffffffffu, s1, m);
                s2 += __shfl_xor_sync(0xffffffffu, s2, m);
            }
            if (ks == 0) {
                parts[(R0r+0)*16 + b] = s0;
                parts[(R0r+1)*16 + b] = s1;
                parts[(R0r+2)*16 + b] = s2;
            }
        }
        __syncthreads();
        // phase 2: gate math, write h_next to global
        float* hdst = ((t+1) & 1) ? hd1 : hd0;
        if (oact) {
            float ghr = br + parts[prI];
            float ghz = bz + parts[pzI];
            float ghn = bn + parts[pnI];
            float r = 1.f/(1.f + expf(-(xr + ghr)));
            float z = 1.f/(1.f + expf(-(xz + ghz)));
            float n = tanhf(xn + r*ghn);
            hdst[hoff] = (1.f - z)*n + z*h_s[hpI];
        }
        __threadfence();
        __syncthreads();
        if (tid == 0) bar_arrive_wait(bar + t, need);
        __syncthreads();
        if (t+1 < T) {
            int nb = (t+1) & 1;
            if (!isQ) {
                int row = tid >> 6, col = tid & 63;   // 8 rows x 64 float4
                int chain = row >> 2, b = row & 3;
                const float* src = (chain ? g_ha[nb] : g_hc[nb]) + (size_t)(bg*4 + b)*256;
                ((float4*)h_s)[row*64 + col] = __ldcg((const float4*)src + col);
            } else {
                #pragma unroll
                for (int i = 0; i < 2; i++) {
                    int idx = tid + i*512;            // 16 rows x 64 float4
                    int row = idx >> 6, col = idx & 63;
                    const float* src = g_hq[nb] + (size_t)(bg*16 + row)*256;
                    ((float4*)h_s)[row*64 + col] = __ldcg((const float4*)src + col);
                }
            }
            __syncthreads();
        }
    }
}

// ---------------- K3: position dense, W reused across all 24 docs ------------
__global__ void __launch_bounds__(256) posdense_k(
    const float* __restrict__ posW, const float* __restrict__ posb,
    const float* __restrict__ ptab) {
    __shared__ float in_s[24*260];
    int c0 = blockIdx.x * 32;
    int tid = threadIdx.x;
    for (int i = tid; i < 24*260; i += 256) {
        int d = i / 260, k = i - d*260;
        in_s[i] = (k < 256) ? g_hc[0][d*256 + k] : ptab[(d % 12)*4 + (k - 256)];
    }
    __syncthreads();
    int kg = tid & 7, cx = tid >> 3;
    int c = c0 + cx;
    int k0 = kg*33, k1 = (kg == 7) ? 260 : k0 + 33;
    float acc[24];
    #pragma unroll
    for (int d = 0; d < 24; d++) acc[d] = 0.f;
    const float* wr = posW + (size_t)c*260;
    for (int k = k0; k < k1; k++) {
        float wv = wr[k];
        #pragma unroll
        for (int d = 0; d < 24; d++) acc[d] = fmaf(wv, in_s[d*260 + k], acc[d]);
    }
    #pragma unroll
    for (int d = 0; d < 24; d++) {
        float s = acc[d];
        s += __shfl_xor_sync(0xffffffffu, s, 1);
        s += __shfl_xor_sync(0xffffffffu, s, 2);
        s += __shfl_xor_sync(0xffffffffu, s, 4);
        if (kg == 0) g_cfin[d*256 + c] = s + posb[c];
    }
}

// ---------------- K4: attention memory read ---------------------------------
__global__ void __launch_bounds__(256) attend_k() {
    __shared__ float enc[256];
    __shared__ float wgt[24];
    int q = blockIdx.x, tid = threadIdx.x;
    enc[tid] = g_hq[0][q*256 + tid];
    __syncthreads();
    if (tid < 24) {
        const float* ar = g_ha[0] + tid*256;
        float s = 0.f;
        #pragma unroll 8
        for (int k = 0; k < 256; k += 4) {
            float4 a = *(const float4*)(ar + k);
            s = fmaf(enc[k],a.x,s); s = fmaf(enc[k+1],a.y,s);
            s = fmaf(enc[k+2],a.z,s); s = fmaf(enc[k+3],a.w,s);
        }
        wgt[tid] = s;
    }
    __syncthreads();
    if (tid < 2) {
        int off = tid*12;
        float mx = -1e30f;
        for (int d = 0; d < 12; d++) mx = fmaxf(mx, wgt[off+d]);
        float sum = 0.f;
        for (int d = 0; d < 12; d++) { float e = expf(wgt[off+d]-mx); wgt[off+d]=e; sum += e; }
        float inv = 1.f/sum;
        for (int d = 0; d < 12; d++) wgt[off+d] *= inv;
    }
    __syncthreads();
    float v = enc[tid];
    #pragma unroll
    for (int d = 0; d < 24; d++) v = fmaf(wgt[d], g_cfin[d*256 + tid], v);
    g_qpn[q*256 + tid] = v;
}

// ---------------- K5: gi2 = qpn @ qWih^T + qbih ------------------------------
__global__ void __launch_bounds__(256) gemm2_k(const float* __restrict__ W,
                                               const float* __restrict__ bias) {
    int n0 = blockIdx.x * 64;
    __shared__ float As[32][68];
    __shared__ float Bs[32][68];
    int tid = threadIdx.x;
    int tx = tid & 15, ty = tid >> 4;
    float acc[4][4] = {};
    for (int k0 = 0; k0 < HID; k0 += 32) {
        #pragma unroll
        for (int i = 0; i < 2; i++) {
            int idx = tid + i*256;
            int m = idx >> 3, kk = (idx & 7) << 2;
            float4 v = *(const float4*)(g_qpn + (size_t)m*HID + k0 + kk);
            As[kk+0][m]=v.x; As[kk+1][m]=v.y; As[kk+2][m]=v.z; As[kk+3][m]=v.w;
            float4 u = *(const float4*)(W + (size_t)(n0+m)*HID + k0 + kk);
            Bs[kk+0][m]=u.x; Bs[kk+1][m]=u.y; Bs[kk+2][m]=u.z; Bs[kk+3][m]=u.w;
        }
        __syncthreads();
        #pragma unroll
        for (int k = 0; k < 32; k++) {
            float a[4], b[4];
            #pragma unroll
            for (int i=0;i<4;i++) a[i] = As[k][ty*4+i];
            #pragma unroll
            for (int j=0;j<4;j++) b[j] = Bs[k][tx*4+j];
            #pragma unroll
            for (int i=0;i<4;i++)
                #pragma unroll
                for (int j=0;j<4;j++) acc[i][j] = fmaf(a[i], b[j], acc[i][j]);
        }
        __syncthreads();
    }
    #pragma unroll
    for (int i=0;i<4;i++) {
        int m = ty*4 + i;
        int n = n0 + tx*4;
        float4 o;
        o.x = acc[i][0] + bias[n+0];
        o.y = acc[i][1] + bias[n+1];
        o.z = acc[i][2] + bias[n+2];
        o.w = acc[i][3] + bias[n+3];
        *(float4*)(g_gi2 + (size_t)m*768 + n) = o;
    }
}

// ---------------- K6: final gate (h0 = 0) ------------------------------------
__global__ void __launch_bounds__(256) gate_k(const float* __restrict__ qbhh,
                                              float* __restrict__ out) {
    int q = blockIdx.x, c = threadIdx.x;
    const float* g = g_gi2 + (size_t)q*768;
    float r = 1.f/(1.f + expf(-(g[c]     + qbhh[c])));
    float z = 1.f/(1.f + expf(-(g[256+c] + qbhh[256+c])));
    float n = tanhf(g[512+c] + r*qbhh[512+c]);
    out[q*256 + c] = (1.f - z)*n;
}

// ---------------- launch ------------------------------------------------------
extern "C" void kernel_launch(void* const* d_in, const int* in_sizes, int n_in,
                              void* d_out, int out_size) {
    const int*   qt   = (const int*)d_in[0];
    const int*   pt   = (const int*)d_in[1];
    const int*   nt   = (const int*)d_in[2];
    const float* temb = (const float*)d_in[3];
    const float* tWih = (const float*)d_in[4];
    const float* tWhh = (const float*)d_in[5];
    const float* tbih = (const float*)d_in[6];
    const float* tbhh = (const float*)d_in[7];
    const float* demb = (const float*)d_in[8];
    const float* cWih = (const float*)d_in[9];
    const float* cWhh = (const float*)d_in[10];
    const float* cbih = (const float*)d_in[11];
    const float* cbhh = (const float*)d_in[12];
    const float* aWih = (const float*)d_in[13];
    const float* aWhh = (const float*)d_in[14];
    const float* abih = (const float*)d_in[15];
    const float* abhh = (const float*)d_in[16];
    const float* ptab = (const float*)d_in[17];
    const float* posW = (const float*)d_in[18];
    const float* posb = (const float*)d_in[19];
    const float* qWih = (const float*)d_in[20];
    const float* qbih = (const float*)d_in[22];
    const float* qbhh = (const float*)d_in[23];

    void* barp = nullptr;
    cudaGetSymbolAddress(&barp, g_bar);
    cudaMemsetAsync(barp, 0, sizeof(unsigned)*512);

    gi_gemm_k<<<360, 256>>>(qt, pt, nt, temb, demb,
                            tWih, tbih, cWih, cbih, aWih, abih);
    scan_k<<<DOC_CTAS + Q_CTAS, 512>>>(tWhh, tbhh, cWhh, cbhh, aWhh, abhh);
    posdense_k<<<8, 256>>>(posW, posb, ptab);
    attend_k<<<QN, 256>>>();
    gemm2_k<<<12, 256>>>(qWih, qbih);
    gate_k<<<QN, 256>>>(qbhh, (float*)d_out);
}

// round 5
// speedup vs baseline: 3.1714x; 1.4726x over previous
#include <cuda_runtime.h>
#include <math.h>

#define HID 256
#define QN 64
#define LQ 20
#define DN 24
#define LD 50
#define QROWS (QN*LQ)   // 1280
#define DROWS (DN*LD)   // 1200

typedef unsigned long long u64;

__device__ __forceinline__ u64 ffma2(u64 a, u64 b, u64 c) {
    u64 d; asm("fma.rn.f32x2 %0, %1, %2, %3;" : "=l"(d) : "l"(a), "l"(b), "l"(c)); return d;
}
__device__ __forceinline__ float hsum2(u64 s) {
    float lo, hi; asm("mov.b64 {%0, %1}, %2;" : "=f"(lo), "=f"(hi) : "l"(s)); return lo + hi;
}
__device__ __forceinline__ void unpack2(u64 s, float& lo, float& hi) {
    asm("mov.b64 {%0, %1}, %2;" : "=f"(lo), "=f"(hi) : "l"(s));
}
__device__ __forceinline__ u64 dupf(float v) {
    u64 d; asm("mov.b64 %0, {%1, %1};" : "=l"(d) : "f"(v)); return d;
}
__device__ __forceinline__ float dot4(float4 a, float4 b, float s) {
    s = fmaf(a.x, b.x, s); s = fmaf(a.y, b.y, s);
    s = fmaf(a.z, b.z, s); s = fmaf(a.w, b.w, s);
    return s;
}

// ---------------- scratch ----------------------------------------------------
__device__ __align__(16) float g_giq[QROWS*768];
__device__ __align__(16) float g_gic[DROWS*768];
__device__ __align__(16) float g_gia[DROWS*768];
__device__ __align__(16) float g_hq[2][QN*HID];
__device__ __align__(16) float g_hc[2][DN*HID];
__device__ __align__(16) float g_ha[2][DN*HID];
__device__ __align__(16) float g_cfin[DN*HID];
__device__ unsigned g_bar[512];

// ---------------- K1: gi = emb[tok] @ W^T + b, gather fused, f32x2 -----------
#define GBM 128
#define GBN 192
#define GBK 32
#define ASD 132
#define BSD 196

__global__ void __launch_bounds__(256) gi_gemm_k(
    const int* __restrict__ qt, const int* __restrict__ pt, const int* __restrict__ nt,
    const float* __restrict__ temb, const float* __restrict__ demb,
    const float* __restrict__ tW, const float* __restrict__ tb,
    const float* __restrict__ cW, const float* __restrict__ cb,
    const float* __restrict__ aW, const float* __restrict__ ab) {
    __shared__ float As[GBK*ASD];
    __shared__ float Bs[GBK*BSD];
    __shared__ int toks[GBM];

    int bid = blockIdx.x;
    int seg = bid / 40;          // 0=query, 1=doc-c, 2=doc-a
    int rem = bid - seg*40;
    int mtl = rem >> 2, ntl = rem & 3;
    int m0 = mtl*GBM, n0 = ntl*GBN;

    const float* W; const float* bias; float* C; const float* emb; int M;
    if (seg == 0)      { W=tW; bias=tb; C=g_giq; emb=temb; M=QROWS; }
    else if (seg == 1) { W=cW; bias=cb; C=g_gic; emb=demb; M=DROWS; }
    else               { W=aW; bias=ab; C=g_gia; emb=demb; M=DROWS; }

    int tid = threadIdx.x;
    if (tid < GBM) {
        int m = m0 + tid;
        int tk = 0;
        if (m < M) {
            if (seg == 0) tk = qt[m];
            else tk = (m < 600) ? pt[m] : nt[m-600];
        }
        toks[tid] = tk;
    }
    __syncthreads();

    int tx = tid & 15, ty = tid >> 4;
    u64 acc2[4][12];
    #pragma unroll
    for (int p = 0; p < 4; p++)
        #pragma unroll
        for (int j = 0; j < 12; j++) acc2[p][j] = 0ull;

    for (int k0 = 0; k0 < HID; k0 += GBK) {
        // fill A: [32k][128m]
        #pragma unroll
        for (int q = 0; q < 4; q++) {
            int idx = q*256 + tid;           // 0..1023
            int kq = idx >> 7, m = idx & 127;
            float4 v = make_float4(0.f,0.f,0.f,0.f);
            if (m0 + m < M) v = *(const float4*)(emb + (size_t)toks[m]*HID + k0 + kq*4);
            As[(kq*4+0)*ASD + m] = v.x; As[(kq*4+1)*ASD + m] = v.y;
            As[(kq*4+2)*ASD + m] = v.z; As[(kq*4+3)*ASD + m] = v.w;
        }
        // fill B: [32k][192n]
        #pragma unroll
        for (int q = 0; q < 6; q++) {
            int idx = q*256 + tid;           // 0..1535
            int kq = idx / 192, n = idx - kq*192;
            float4 v = *(const float4*)(W + (size_t)(n0+n)*HID + k0 + kq*4);
            Bs[(kq*4+0)*BSD + n] = v.x; Bs[(kq*4+1)*BSD + n] = v.y;
            Bs[(kq*4+2)*BSD + n] = v.z; Bs[(kq*4+3)*BSD + n] = v.w;
        }
        __syncthreads();
        #pragma unroll 8
        for (int k = 0; k < GBK; k++) {
            ulonglong2 A01 = *(const ulonglong2*)(As + k*ASD + ty*8);
            ulonglong2 A23 = *(const ulonglong2*)(As + k*ASD + ty*8 + 4);
            u64 a2[4] = {A01.x, A01.y, A23.x, A23.y};
            float4 b0 = *(const float4*)(Bs + k*BSD + tx*4);
            float4 b1 = *(const float4*)(Bs + k*BSD + 64 + tx*4);
            float4 b2 = *(const float4*)(Bs + k*BSD + 128 + tx*4);
            u64 bb[12];
            bb[0]=dupf(b0.x); bb[1]=dupf(b0.y); bb[2]=dupf(b0.z); bb[3]=dupf(b0.w);
            bb[4]=dupf(b1.x); bb[5]=dupf(b1.y); bb[6]=dupf(b1.z); bb[7]=dupf(b1.w);
            bb[8]=dupf(b2.x); bb[9]=dupf(b2.y); bb[10]=dupf(b2.z); bb[11]=dupf(b2.w);
            #pragma unroll
            for (int p = 0; p < 4; p++)
                #pragma unroll
                for (int j = 0; j < 12; j++)
                    acc2[p][j] = ffma2(a2[p], bb[j], acc2[p][j]);
        }
        __syncthreads();
    }

    // epilogue
    float4 bv[3];
    #pragma unroll
    for (int g = 0; g < 3; g++)
        bv[g] = *(const float4*)(bias + n0 + g*64 + tx*4);
    #pragma unroll
    for (int p = 0; p < 4; p++) {
        float vlo[12], vhi[12];
        #pragma unroll
        for (int j = 0; j < 12; j++) unpack2(acc2[p][j], vlo[j], vhi[j]);
        #pragma unroll
        for (int e = 0; e < 2; e++) {
            int m = m0 + ty*8 + p*2 + e;
            if (m >= M) continue;
            const float* vv = e ? vhi : vlo;
            #pragma unroll
            for (int g = 0; g < 3; g++) {
                float4 o;
                o.x = vv[g*4+0] + (&bv[g].x)[0];
                o.y = vv[g*4+1] + (&bv[g].x)[1];
                o.z = vv[g*4+2] + (&bv[g].x)[2];
                o.w = vv[g*4+3] + (&bv[g].x)[3];
                *(float4*)(C + (size_t)m*768 + n0 + g*64 + tx*4) = o;
            }
        }
    }
}

// ---------------- K2: GRU scans, f32x2, W in regs, k-split 4 -----------------
__device__ __forceinline__ void bar_arrive_wait(unsigned* p, unsigned need) {
    asm volatile("red.release.gpu.global.add.u32 [%0], %1;" :: "l"(p), "r"(1u) : "memory");
    unsigned v;
    do {
        asm volatile("ld.acquire.gpu.global.u32 %0, [%1];" : "=r"(v) : "l"(p) : "memory");
    } while (v < need);
}

__global__ void __launch_bounds__(512) scan_k(
    const float* __restrict__ tWhh, const float* __restrict__ tbhh,
    const float* __restrict__ cWhh, const float* __restrict__ cbhh,
    const float* __restrict__ aWhh, const float* __restrict__ abhh) {
    __shared__ float h_s[16*256];
    __shared__ float parts[96*17];

    int bid = blockIdx.x, tid = threadIdx.x;
    bool isQ = (bid >= 96);
    int lane = tid & 31;
    int r = lane & 7, ks = lane >> 3;
    int row = (tid >> 5)*8 + r;
    bool act = tid < 384;

    int bg, c0, T, PB;
    unsigned* bar; unsigned need;
    if (!isQ) { bg = bid >> 4; c0 = (bid & 15) << 4; T = LD; PB = 5;  bar = g_bar + bg*64;        need = 16; }
    else { int qg = bid - 96; bg = qg >> 3; c0 = (qg & 7) << 5; T = LQ; PB = 17; bar = g_bar + 384 + bg*32; need = 8; }

    // ---- W slice into registers (rotated chunk order for conflict-free h LDS)
    u64 wreg[32];
    int hrow0 = 0;
    if (act) {
        const float* Wp; int grow;
        if (!isQ) {
            int chain = row / 48, rr = row - (row/48)*48;
            grow = (rr >> 4)*256 + c0 + (rr & 15);
            Wp = chain ? aWhh : cWhh;
            hrow0 = chain * 4;
        } else {
            grow = (row >> 5)*256 + c0 + (row & 31);
            Wp = tWhh;
        }
        const float* base = Wp + (size_t)grow*HID + ks*64;
        #pragma unroll
        for (int i = 0; i < 8; i++) {
            int ch = (i + ks) & 7;
            ulonglong2 p0 = *(const ulonglong2*)(base + ch*8);
            ulonglong2 p1 = *(const ulonglong2*)(base + ch*8 + 4);
            wreg[i*4+0]=p0.x; wreg[i*4+1]=p0.y; wreg[i*4+2]=p1.x; wreg[i*4+3]=p1.y;
        }
    }

    // ---- phase-2 setup ---------------------------------------------------------
    bool oact; int prI=0, pzI=0, pnI=0, hpI=0, hoff=0, cc=0;
    float br=0.f, bz=0.f, bn=0.f;
    const float* giBase = nullptr;
    int docChain = 0;
    if (!isQ) {
        oact = (tid < 128);
        if (oact) {
            int chain = tid >> 6, b = (tid >> 4) & 3, cl = tid & 15;
            docChain = chain;
            cc = c0 + cl;
            prI = (chain*48 + cl)*PB + b; pzI = prI + 16*PB; pnI = prI + 32*PB;
            hpI = (chain*4 + b)*256 + cc;
            const float* bh = chain ? abhh : cbhh;
            br = bh[cc]; bz = bh[256+cc]; bn = bh[512+cc];
            giBase = (chain ? g_gia : g_gic) + (size_t)(bg*4 + b)*LD*768;
            hoff = (bg*4 + b)*256 + cc;
        }
    } else {
        oact = true;
        int b = tid >> 5, cl = tid & 31;
        cc = c0 + cl;
        prI = cl*PB + b; pzI = (32+cl)*PB + b; pnI = (64+cl)*PB + b;
        hpI = b*256 + cc;
        br = tbhh[cc]; bz = tbhh[256+cc]; bn = tbhh[512+cc];
        giBase = g_giq + (size_t)(bg*16 + b)*LQ*768;
        hoff = (bg*16 + b)*256 + cc;
    }

    // ---- zero h ----------------------------------------------------------------
    #pragma unroll
    for (int i = 0; i < 2; i++)
        ((float4*)h_s)[tid + i*512] = make_float4(0.f,0.f,0.f,0.f);
    __syncthreads();

    for (int t = 0; t < T; t++) {
        float xr=0.f, xz=0.f, xn=0.f;
        if (oact) {
            const float* gp = giBase + (size_t)t*768;
            xr = gp[cc]; xz = gp[256+cc]; xn = gp[512+cc];
        }
        // phase 1
        if (act) {
            if (!isQ) {
                u64 acc[4];
                #pragma unroll
                for (int b = 0; b < 4; b++) acc[b] = 0ull;
                #pragma unroll
                for (int i = 0; i < 8; i++) {
                    int off = ((i + ks) & 7) * 8 + ks*64;
                    #pragma unroll
                    for (int b = 0; b < 4; b++) {
                        const float* hp = h_s + (hrow0 + b)*256 + off;
                        ulonglong2 h0 = *(const ulonglong2*)hp;
                        ulonglong2 h1 = *(const ulonglong2*)(hp + 4);
                        acc[b] = ffma2(h0.x, wreg[i*4+0], acc[b]);
                        acc[b] = ffma2(h0.y, wreg[i*4+1], acc[b]);
                        acc[b] = ffma2(h1.x, wreg[i*4+2], acc[b]);
                        acc[b] = ffma2(h1.y, wreg[i*4+3], acc[b]);
                    }
                }
                #pragma unroll
                for (int b = 0; b < 4; b++) {
                    float s = hsum2(acc[b]);
                    s += __shfl_xor_sync(0xffffffffu, s, 8);
                    s += __shfl_xor_sync(0xffffffffu, s, 16);
                    if (ks == 0) parts[row*5 + b] = s;
                }
            } else {
                #pragma unroll
                for (int half = 0; half < 2; half++) {
                    u64 acc[8];
                    #pragma unroll
                    for (int b = 0; b < 8; b++) acc[b] = 0ull;
                    #pragma unroll
                    for (int i = 0; i < 8; i++) {
                        int off = ((i + ks) & 7) * 8 + ks*64;
                        #pragma unroll
                        for (int b = 0; b < 8; b++) {
                            const float* hp = h_s + (half*8 + b)*256 + off;
                            ulonglong2 h0 = *(const ulonglong2*)hp;
                            ulonglong2 h1 = *(const ulonglong2*)(hp + 4);
                            acc[b] = ffma2(h0.x, wreg[i*4+0], acc[b]);
                            acc[b] = ffma2(h0.y, wreg[i*4+1], acc[b]);
                            acc[b] = ffma2(h1.x, wreg[i*4+2], acc[b]);
                            acc[b] = ffma2(h1.y, wreg[i*4+3], acc[b]);
                        }
                    }
                    #pragma unroll
                    for (int b = 0; b < 8; b++) {
                        float s = hsum2(acc[b]);
                        s += __shfl_xor_sync(0xffffffffu, s, 8);
                        s += __shfl_xor_sync(0xffffffffu, s, 16);
                        if (ks == 0) parts[row*17 + half*8 + b] = s;
                    }
                }
            }
        }
        __syncthreads();
        // phase 2
        int nb = (t+1) & 1;
        if (oact) {
            float ghr = br + parts[prI];
            float ghz = bz + parts[pzI];
            float ghn = bn + parts[pnI];
            float rr2 = 1.f/(1.f + expf(-(xr + ghr)));
            float zz = 1.f/(1.f + expf(-(xz + ghz)));
            float nn = tanhf(xn + rr2*ghn);
            float hv = (1.f - zz)*nn + zz*h_s[hpI];
            float* hdst;
            if (!isQ) hdst = docChain ? g_ha[nb] : g_hc[nb];
            else      hdst = g_hq[nb];
            hdst[hoff] = hv;
        }
        __syncthreads();
        if (tid == 0) bar_arrive_wait(bar + t, need);
        __syncthreads();
        if (t+1 < T) {
            if (!isQ) {
                int rw = tid >> 6, col = tid & 63;     // 8 rows x 64 float4
                int chain = rw >> 2, b = rw & 3;
                const float* src = (chain ? g_ha[nb] : g_hc[nb]) + (size_t)(bg*4 + b)*256;
                ((float4*)h_s)[rw*64 + col] = __ldcg((const float4*)src + col);
            } else {
                #pragma unroll
                for (int i = 0; i < 2; i++) {
                    int idx = tid + i*512;
                    int rw = idx >> 6, col = idx & 63;
                    const float* src = g_hq[nb] + (size_t)(bg*16 + rw)*256;
                    ((float4*)h_s)[rw*64 + col] = __ldcg((const float4*)src + col);
                }
            }
            __syncthreads();
        }
    }
}

// ---------------- K3: position dense ----------------------------------------
__global__ void __launch_bounds__(256) posdense_k(
    const float* __restrict__ posW, const float* __restrict__ posb,
    const float* __restrict__ ptab) {
    __shared__ float in_s[24*260];
    int c0 = blockIdx.x * 32;
    int tid = threadIdx.x;
    for (int i = tid; i < 24*260; i += 256) {
        int d = i / 260, k = i - d*260;
        in_s[i] = (k < 256) ? g_hc[0][d*256 + k] : ptab[(d % 12)*4 + (k - 256)];
    }
    __syncthreads();
    int kg = tid & 7, cx = tid >> 3;
    int c = c0 + cx;
    int k0 = kg*33, k1 = (kg == 7) ? 260 : k0 + 33;
    float acc[24];
    #pragma unroll
    for (int d = 0; d < 24; d++) acc[d] = 0.f;
    const float* wr = posW + (size_t)c*260;
    for (int k = k0; k < k1; k++) {
        float wv = wr[k];
        #pragma unroll
        for (int d = 0; d < 24; d++) acc[d] = fmaf(wv, in_s[d*260 + k], acc[d]);
    }
    #pragma unroll
    for (int d = 0; d < 24; d++) {
        float s = acc[d];
        s += __shfl_xor_sync(0xffffffffu, s, 1);
        s += __shfl_xor_sync(0xffffffffu, s, 2);
        s += __shfl_xor_sync(0xffffffffu, s, 4);
        if (kg == 0) g_cfin[d*256 + c] = s + posb[c];
    }
}

// ---------------- K4: fused attend + final GRU (h0=0) ------------------------
__global__ void __launch_bounds__(256) final_k(const float* __restrict__ qWih,
                                               const float* __restrict__ qbih,
                                               const float* __restrict__ qbhh,
                                               float* __restrict__ out) {
    __shared__ float enc[256];
    __shared__ float wgt[24];
    __shared__ float qs[256];
    int q = blockIdx.x, tid = threadIdx.x;
    enc[tid] = g_hq[0][q*256 + tid];
    __syncthreads();
    if (tid < 192) {
        int d = tid >> 3, sg = tid & 7;
        const float4* ar = (const float4*)(g_ha[0] + d*256 + sg*32);
        const float4* er = (const float4*)(enc + sg*32);
        float s = 0.f;
        #pragma unroll
        for (int i = 0; i < 8; i++) s = dot4(er[i], ar[i], s);
        s += __shfl_xor_sync(0xffffffffu, s, 1);
        s += __shfl_xor_sync(0xffffffffu, s, 2);
        s += __shfl_xor_sync(0xffffffffu, s, 4);
        if (sg == 0) wgt[d] = s;
    }
    __syncthreads();
    if (tid < 2) {
        int off = tid*12;
        float mx = -1e30f;
        for (int d = 0; d < 12; d++) mx = fmaxf(mx, wgt[off+d]);
        float sum = 0.f;
        for (int d = 0; d < 12; d++) { float e = expf(wgt[off+d]-mx); wgt[off+d]=e; sum += e; }
        float inv = 1.f/sum;
        for (int d = 0; d < 12; d++) wgt[off+d] *= inv;
    }
    __syncthreads();
    {
        float v = enc[tid];
        #pragma unroll
        for (int d = 0; d < 24; d++) v = fmaf(wgt[d], g_cfin[d*256 + tid], v);
        qs[tid] = v;
    }
    __syncthreads();
    float a0 = qbih[tid], a1 = qbih[256+tid], a2 = qbih[512+tid];
    const float4* w0 = (const float4*)(qWih + (size_t)tid*256);
    const float4* w1 = (const float4*)(qWih + (size_t)(256+tid)*256);
    const float4* w2 = (const float4*)(qWih + (size_t)(512+tid)*256);
    const float4* xs = (const float4*)qs;
    #pragma unroll 8
    for (int i = 0; i < 64; i++) {
        float4 x = xs[i];
        a0 = dot4(x, w0[i], a0);
        a1 = dot4(x, w1[i], a1);
        a2 = dot4(x, w2[i], a2);
    }
    float r = 1.f/(1.f + expf(-(a0 + qbhh[tid])));
    float z = 1.f/(1.f + expf(-(a1 + qbhh[256+tid])));
    float n = tanhf(a2 + r*qbhh[512+tid]);
    out[q*256 + tid] = (1.f - z)*n;
}

// ---------------- launch ------------------------------------------------------
extern "C" void kernel_launch(void* const* d_in, const int* in_sizes, int n_in,
                              void* d_out, int out_size) {
    const int*   qt   = (const int*)d_in[0];
    const int*   pt   = (const int*)d_in[1];
    const int*   nt   = (const int*)d_in[2];
    const float* temb = (const float*)d_in[3];
    const float* tWih = (const float*)d_in[4];
    const float* tWhh = (const float*)d_in[5];
    const float* tbih = (const float*)d_in[6];
    const float* tbhh = (const float*)d_in[7];
    const float* demb = (const float*)d_in[8];
    const float* cWih = (const float*)d_in[9];
    const float* cWhh = (const float*)d_in[10];
    const float* cbih = (const float*)d_in[11];
    const float* cbhh = (const float*)d_in[12];
    const float* aWih = (const float*)d_in[13];
    const float* aWhh = (const float*)d_in[14];
    const float* abih = (const float*)d_in[15];
    const float* abhh = (const float*)d_in[16];
    const float* ptab = (const float*)d_in[17];
    const float* posW = (const float*)d_in[18];
    const float* posb = (const float*)d_in[19];
    const float* qWih = (const float*)d_in[20];
    const float* qbih = (const float*)d_in[22];
    const float* qbhh = (const float*)d_in[23];

    void* barp = nullptr;
    cudaGetSymbolAddress(&barp, g_bar);
    cudaMemsetAsync(barp, 0, sizeof(unsigned)*512);

    gi_gemm_k<<<120, 256>>>(qt, pt, nt, temb, demb,
                            tWih, tbih, cWih, cbih, aWih, abih);
    scan_k<<<128, 512>>>(tWhh, tbhh, cWhh, cbhh, aWhh, abhh);
    posdense_k<<<8, 256>>>(posW, posb, ptab);
    final_k<<<QN, 256>>>(qWih, qbih, qbhh, (float*)d_out);
}

// round 6
// speedup vs baseline: 3.2236x; 1.0165x over previous
#include <cuda_runtime.h>
#include <math.h>

#define HID 256
#define QN 64
#define LQ 20
#define DN 24
#define LD 50
#define QROWS (QN*LQ)   // 1280
#define DROWS (DN*LD)   // 1200

typedef unsigned long long u64;

__device__ __forceinline__ u64 ffma2(u64 a, u64 b, u64 c) {
    u64 d; asm("fma.rn.f32x2 %0, %1, %2, %3;" : "=l"(d) : "l"(a), "l"(b), "l"(c)); return d;
}
__device__ __forceinline__ float hsum2(u64 s) {
    float lo, hi; asm("mov.b64 {%0, %1}, %2;" : "=f"(lo), "=f"(hi) : "l"(s)); return lo + hi;
}
__device__ __forceinline__ void unpack2(u64 s, float& lo, float& hi) {
    asm("mov.b64 {%0, %1}, %2;" : "=f"(lo), "=f"(hi) : "l"(s));
}
__device__ __forceinline__ u64 dupf(float v) {
    u64 d; asm("mov.b64 %0, {%1, %1};" : "=l"(d) : "f"(v)); return d;
}
__device__ __forceinline__ float dot4(float4 a, float4 b, float s) {
    s = fmaf(a.x, b.x, s); s = fmaf(a.y, b.y, s);
    s = fmaf(a.z, b.z, s); s = fmaf(a.w, b.w, s);
    return s;
}

// ---------------- scratch ----------------------------------------------------
__device__ __align__(16) float g_giq[QROWS*768];
__device__ __align__(16) float g_gic[DROWS*768];
__device__ __align__(16) float g_gia[DROWS*768];
__device__ __align__(16) float g_hq[2][QN*HID];
__device__ __align__(16) float g_hc[2][DN*HID];
__device__ __align__(16) float g_ha[2][DN*HID];
__device__ __align__(16) float g_cfin[DN*HID];
__device__ __align__(16) float g_qpn[QN*HID];
__device__ __align__(16) unsigned g_bar[512];

// ---------------- K1: gi = emb[tok] @ W^T + b, gather fused, f32x2 -----------
#define GBM 128
#define GBN 192
#define GBK 32
#define ASD 132
#define BSD 196

__global__ void __launch_bounds__(256) gi_gemm_k(
    const int* __restrict__ qt, const int* __restrict__ pt, const int* __restrict__ nt,
    const float* __restrict__ temb, const float* __restrict__ demb,
    const float* __restrict__ tW, const float* __restrict__ tb,
    const float* __restrict__ cW, const float* __restrict__ cb,
    const float* __restrict__ aW, const float* __restrict__ ab) {
    __shared__ float As[GBK*ASD];
    __shared__ float Bs[GBK*BSD];
    __shared__ int toks[GBM];

    int bid = blockIdx.x;
    int tid = threadIdx.x;
    // zero the scan barriers here (scan_k runs after this kernel in-stream)
    if (bid == 0 && tid < 128)
        ((float4*)g_bar)[tid] = make_float4(0.f,0.f,0.f,0.f);

    int seg = bid / 40;          // 0=query, 1=doc-c, 2=doc-a
    int rem = bid - seg*40;
    int mtl = rem >> 2, ntl = rem & 3;
    int m0 = mtl*GBM, n0 = ntl*GBN;

    const float* W; const float* bias; float* C; const float* emb; int M;
    if (seg == 0)      { W=tW; bias=tb; C=g_giq; emb=temb; M=QROWS; }
    else if (seg == 1) { W=cW; bias=cb; C=g_gic; emb=demb; M=DROWS; }
    else               { W=aW; bias=ab; C=g_gia; emb=demb; M=DROWS; }

    if (tid < GBM) {
        int m = m0 + tid;
        int tk = 0;
        if (m < M) {
            if (seg == 0) tk = qt[m];
            else tk = (m < 600) ? pt[m] : nt[m-600];
        }
        toks[tid] = tk;
    }
    __syncthreads();

    int tx = tid & 15, ty = tid >> 4;
    u64 acc2[4][12];
    #pragma unroll
    for (int p = 0; p < 4; p++)
        #pragma unroll
        for (int j = 0; j < 12; j++) acc2[p][j] = 0ull;

    for (int k0 = 0; k0 < HID; k0 += GBK) {
        #pragma unroll
        for (int q = 0; q < 4; q++) {
            int idx = q*256 + tid;
            int kq = idx >> 7, m = idx & 127;
            float4 v = make_float4(0.f,0.f,0.f,0.f);
            if (m0 + m < M) v = *(const float4*)(emb + (size_t)toks[m]*HID + k0 + kq*4);
            As[(kq*4+0)*ASD + m] = v.x; As[(kq*4+1)*ASD + m] = v.y;
            As[(kq*4+2)*ASD + m] = v.z; As[(kq*4+3)*ASD + m] = v.w;
        }
        #pragma unroll
        for (int q = 0; q < 6; q++) {
            int idx = q*256 + tid;
            int kq = idx / 192, n = idx - kq*192;
            float4 v = *(const float4*)(W + (size_t)(n0+n)*HID + k0 + kq*4);
            Bs[(kq*4+0)*BSD + n] = v.x; Bs[(kq*4+1)*BSD + n] = v.y;
            Bs[(kq*4+2)*BSD + n] = v.z; Bs[(kq*4+3)*BSD + n] = v.w;
        }
        __syncthreads();
        #pragma unroll 8
        for (int k = 0; k < GBK; k++) {
            ulonglong2 A01 = *(const ulonglong2*)(As + k*ASD + ty*8);
            ulonglong2 A23 = *(const ulonglong2*)(As + k*ASD + ty*8 + 4);
            u64 a2[4] = {A01.x, A01.y, A23.x, A23.y};
            float4 b0 = *(const float4*)(Bs + k*BSD + tx*4);
            float4 b1 = *(const float4*)(Bs + k*BSD + 64 + tx*4);
            float4 b2 = *(const float4*)(Bs + k*BSD + 128 + tx*4);
            u64 bb[12];
            bb[0]=dupf(b0.x); bb[1]=dupf(b0.y); bb[2]=dupf(b0.z); bb[3]=dupf(b0.w);
            bb[4]=dupf(b1.x); bb[5]=dupf(b1.y); bb[6]=dupf(b1.z); bb[7]=dupf(b1.w);
            bb[8]=dupf(b2.x); bb[9]=dupf(b2.y); bb[10]=dupf(b2.z); bb[11]=dupf(b2.w);
            #pragma unroll
            for (int p = 0; p < 4; p++)
                #pragma unroll
                for (int j = 0; j < 12; j++)
                    acc2[p][j] = ffma2(a2[p], bb[j], acc2[p][j]);
        }
        __syncthreads();
    }

    float4 bv[3];
    #pragma unroll
    for (int g = 0; g < 3; g++)
        bv[g] = *(const float4*)(bias + n0 + g*64 + tx*4);
    #pragma unroll
    for (int p = 0; p < 4; p++) {
        float vlo[12], vhi[12];
        #pragma unroll
        for (int j = 0; j < 12; j++) unpack2(acc2[p][j], vlo[j], vhi[j]);
        #pragma unroll
        for (int e = 0; e < 2; e++) {
            int m = m0 + ty*8 + p*2 + e;
            if (m >= M) continue;
            const float* vv = e ? vhi : vlo;
            #pragma unroll
            for (int g = 0; g < 3; g++) {
                float4 o;
                o.x = vv[g*4+0] + (&bv[g].x)[0];
                o.y = vv[g*4+1] + (&bv[g].x)[1];
                o.z = vv[g*4+2] + (&bv[g].x)[2];
                o.w = vv[g*4+3] + (&bv[g].x)[3];
                *(float4*)(C + (size_t)m*768 + n0 + g*64 + tx*4) = o;
            }
        }
    }
}

// ---------------- K2: GRU scans, f32x2, W in regs, k-split 4 -----------------
__device__ __forceinline__ void bar_arrive_wait(unsigned* p, unsigned need) {
    asm volatile("red.release.gpu.global.add.u32 [%0], %1;" :: "l"(p), "r"(1u) : "memory");
    unsigned v;
    do {
        asm volatile("ld.acquire.gpu.global.u32 %0, [%1];" : "=r"(v) : "l"(p) : "memory");
    } while (v < need);
}

__global__ void __launch_bounds__(512) scan_k(
    const float* __restrict__ tWhh, const float* __restrict__ tbhh,
    const float* __restrict__ cWhh, const float* __restrict__ cbhh,
    const float* __restrict__ aWhh, const float* __restrict__ abhh) {
    __shared__ float h_s[16*256];
    __shared__ float parts[96*17];

    int bid = blockIdx.x, tid = threadIdx.x;
    bool isQ = (bid >= 96);
    int lane = tid & 31;
    int r = lane & 7, ks = lane >> 3;
    int row = (tid >> 5)*8 + r;
    bool act = tid < 384;

    int bg, c0, T, PB;
    unsigned* bar; unsigned need;
    if (!isQ) { bg = bid >> 4; c0 = (bid & 15) << 4; T = LD; PB = 5;  bar = g_bar + bg*64;        need = 16; }
    else { int qg = bid - 96; bg = qg >> 3; c0 = (qg & 7) << 5; T = LQ; PB = 17; bar = g_bar + 384 + bg*32; need = 8; }

    u64 wreg[32];
    int hrow0 = 0;
    if (act) {
        const float* Wp; int grow;
        if (!isQ) {
            int chain = row / 48, rr = row - (row/48)*48;
            grow = (rr >> 4)*256 + c0 + (rr & 15);
            Wp = chain ? aWhh : cWhh;
            hrow0 = chain * 4;
        } else {
            grow = (row >> 5)*256 + c0 + (row & 31);
            Wp = tWhh;
        }
        const float* base = Wp + (size_t)grow*HID + ks*64;
        #pragma unroll
        for (int i = 0; i < 8; i++) {
            int ch = (i + ks) & 7;
            ulonglong2 p0 = *(const ulonglong2*)(base + ch*8);
            ulonglong2 p1 = *(const ulonglong2*)(base + ch*8 + 4);
            wreg[i*4+0]=p0.x; wreg[i*4+1]=p0.y; wreg[i*4+2]=p1.x; wreg[i*4+3]=p1.y;
        }
    }

    bool oact; int prI=0, pzI=0, pnI=0, hpI=0, hoff=0, cc=0;
    float br=0.f, bz=0.f, bn=0.f;
    const float* giBase = nullptr;
    int docChain = 0;
    if (!isQ) {
        oact = (tid < 128);
        if (oact) {
            int chain = tid >> 6, b = (tid >> 4) & 3, cl = tid & 15;
            docChain = chain;
            cc = c0 + cl;
            prI = (chain*48 + cl)*PB + b; pzI = prI + 16*PB; pnI = prI + 32*PB;
            hpI = (chain*4 + b)*256 + cc;
            const float* bh = chain ? abhh : cbhh;
            br = bh[cc]; bz = bh[256+cc]; bn = bh[512+cc];
            giBase = (chain ? g_gia : g_gic) + (size_t)(bg*4 + b)*LD*768;
            hoff = (bg*4 + b)*256 + cc;
        }
    } else {
        oact = true;
        int b = tid >> 5, cl = tid & 31;
        cc = c0 + cl;
        prI = cl*PB + b; pzI = (32+cl)*PB + b; pnI = (64+cl)*PB + b;
        hpI = b*256 + cc;
        br = tbhh[cc]; bz = tbhh[256+cc]; bn = tbhh[512+cc];
        giBase = g_giq + (size_t)(bg*16 + b)*LQ*768;
        hoff = (bg*16 + b)*256 + cc;
    }

    #pragma unroll
    for (int i = 0; i < 2; i++)
        ((float4*)h_s)[tid + i*512] = make_float4(0.f,0.f,0.f,0.f);
    __syncthreads();

    for (int t = 0; t < T; t++) {
        float xr=0.f, xz=0.f, xn=0.f;
        if (oact) {
            const float* gp = giBase + (size_t)t*768;
            xr = gp[cc]; xz = gp[256+cc]; xn = gp[512+cc];
        }
        if (act) {
            if (!isQ) {
                u64 acc[4];
                #pragma unroll
                for (int b = 0; b < 4; b++) acc[b] = 0ull;
                #pragma unroll
                for (int i = 0; i < 8; i++) {
                    int off = ((i + ks) & 7) * 8 + ks*64;
                    #pragma unroll
                    for (int b = 0; b < 4; b++) {
                        const float* hp = h_s + (hrow0 + b)*256 + off;
                        ulonglong2 h0 = *(const ulonglong2*)hp;
                        ulonglong2 h1 = *(const ulonglong2*)(hp + 4);
                        acc[b] = ffma2(h0.x, wreg[i*4+0], acc[b]);
                        acc[b] = ffma2(h0.y, wreg[i*4+1], acc[b]);
                        acc[b] = ffma2(h1.x, wreg[i*4+2], acc[b]);
                        acc[b] = ffma2(h1.y, wreg[i*4+3], acc[b]);
                    }
                }
                #pragma unroll
                for (int b = 0; b < 4; b++) {
                    float s = hsum2(acc[b]);
                    s += __shfl_xor_sync(0xffffffffu, s, 8);
                    s += __shfl_xor_sync(0xffffffffu, s, 16);
                    if (ks == 0) parts[row*5 + b] = s;
                }
            } else {
                #pragma unroll
                for (int half = 0; half < 2; half++) {
                    u64 acc[8];
                    #pragma unroll
                    for (int b = 0; b < 8; b++) acc[b] = 0ull;
                    #pragma unroll
                    for (int i = 0; i < 8; i++) {
                        int off = ((i + ks) & 7) * 8 + ks*64;
                        #pragma unroll
                        for (int b = 0; b < 8; b++) {
                            const float* hp = h_s + (half*8 + b)*256 + off;
                            ulonglong2 h0 = *(const ulonglong2*)hp;
                            ulonglong2 h1 = *(const ulonglong2*)(hp + 4);
                            acc[b] = ffma2(h0.x, wreg[i*4+0], acc[b]);
                            acc[b] = ffma2(h0.y, wreg[i*4+1], acc[b]);
                            acc[b] = ffma2(h1.x, wreg[i*4+2], acc[b]);
                            acc[b] = ffma2(h1.y, wreg[i*4+3], acc[b]);
                        }
                    }
                    #pragma unroll
                    for (int b = 0; b < 8; b++) {
                        float s = hsum2(acc[b]);
                        s += __shfl_xor_sync(0xffffffffu, s, 8);
                        s += __shfl_xor_sync(0xffffffffu, s, 16);
                        if (ks == 0) parts[row*17 + half*8 + b] = s;
                    }
                }
            }
        }
        __syncthreads();
        int nb = (t+1) & 1;
        if (oact) {
            float ghr = br + parts[prI];
            float ghz = bz + parts[pzI];
            float ghn = bn + parts[pnI];
            float rr2 = 1.f/(1.f + expf(-(xr + ghr)));
            float zz = 1.f/(1.f + expf(-(xz + ghz)));
            float nn = tanhf(xn + rr2*ghn);
            float hv = (1.f - zz)*nn + zz*h_s[hpI];
            float* hdst;
            if (!isQ) hdst = docChain ? g_ha[nb] : g_hc[nb];
            else      hdst = g_hq[nb];
            hdst[hoff] = hv;
        }
        __syncthreads();
        if (tid == 0) bar_arrive_wait(bar + t, need);
        __syncthreads();
        if (t+1 < T) {
            if (!isQ) {
                int rw = tid >> 6, col = tid & 63;
                int chain = rw >> 2, b = rw & 3;
                const float* src = (chain ? g_ha[nb] : g_hc[nb]) + (size_t)(bg*4 + b)*256;
                ((float4*)h_s)[rw*64 + col] = __ldcg((const float4*)src + col);
            } else {
                #pragma unroll
                for (int i = 0; i < 2; i++) {
                    int idx = tid + i*512;
                    int rw = idx >> 6, col = idx & 63;
                    const float* src = g_hq[nb] + (size_t)(bg*16 + rw)*256;
                    ((float4*)h_s)[rw*64 + col] = __ldcg((const float4*)src + col);
                }
            }
            __syncthreads();
        }
    }
}

// ---------------- K3: position dense ----------------------------------------
__global__ void __launch_bounds__(256) posdense_k(
    const float* __restrict__ posW, const float* __restrict__ posb,
    const float* __restrict__ ptab) {
    __shared__ float in_s[24*260];
    int c0 = blockIdx.x * 32;
    int tid = threadIdx.x;
    for (int i = tid; i < 24*260; i += 256) {
        int d = i / 260, k = i - d*260;
        in_s[i] = (k < 256) ? g_hc[0][d*256 + k] : ptab[(d % 12)*4 + (k - 256)];
    }
    __syncthreads();
    int kg = tid & 7, cx = tid >> 3;
    int c = c0 + cx;
    int k0 = kg*33, k1 = (kg == 7) ? 260 : k0 + 33;
    float acc[24];
    #pragma unroll
    for (int d = 0; d < 24; d++) acc[d] = 0.f;
    const float* wr = posW + (size_t)c*260;
    for (int k = k0; k < k1; k++) {
        float wv = wr[k];
        #pragma unroll
        for (int d = 0; d < 24; d++) acc[d] = fmaf(wv, in_s[d*260 + k], acc[d]);
    }
    #pragma unroll
    for (int d = 0; d < 24; d++) {
        float s = acc[d];
        s += __shfl_xor_sync(0xffffffffu, s, 1);
        s += __shfl_xor_sync(0xffffffffu, s, 2);
        s += __shfl_xor_sync(0xffffffffu, s, 4);
        if (kg == 0) g_cfin[d*256 + c] = s + posb[c];
    }
}

// ---------------- K4: attention memory read -> g_qpn -------------------------
__global__ void __launch_bounds__(256) attend_k() {
    __shared__ float enc[256];
    __shared__ float wgt[24];
    int q = blockIdx.x, tid = threadIdx.x;
    enc[tid] = g_hq[0][q*256 + tid];
    __syncthreads();
    if (tid < 192) {
        int d = tid >> 3, sg = tid & 7;
        const float4* ar = (const float4*)(g_ha[0] + d*256 + sg*32);
        const float4* er = (const float4*)(enc + sg*32);
        float s = 0.f;
        #pragma unroll
        for (int i = 0; i < 8; i++) s = dot4(er[i], ar[i], s);
        s += __shfl_xor_sync(0xffffffffu, s, 1);
        s += __shfl_xor_sync(0xffffffffu, s, 2);
        s += __shfl_xor_sync(0xffffffffu, s, 4);
        if (sg == 0) wgt[d] = s;
    }
    __syncthreads();
    if (tid < 2) {
        int off = tid*12;
        float mx = -1e30f;
        for (int d = 0; d < 12; d++) mx = fmaxf(mx, wgt[off+d]);
        float sum = 0.f;
        for (int d = 0; d < 12; d++) { float e = expf(wgt[off+d]-mx); wgt[off+d]=e; sum += e; }
        float inv = 1.f/sum;
        for (int d = 0; d < 12; d++) wgt[off+d] *= inv;
    }
    __syncthreads();
    float v = enc[tid];
    #pragma unroll
    for (int d = 0; d < 24; d++) v = fmaf(wgt[d], g_cfin[d*256 + tid], v);
    g_qpn[q*256 + tid] = v;
}

// ---------------- K5: final GEMM + gate fused, W read once -------------------
// 32 CTAs x 8 cols. 256 threads = 8 warps: (qhalf = w&1, rowgroup = w>>1).
// rows 0..23: row = gate*8 + col. Each thread: q fixed, 6 rows, full K=256.
__global__ void __launch_bounds__(256) gemmgate_k(
    const float* __restrict__ qWih, const float* __restrict__ qbih,
    const float* __restrict__ qbhh, float* __restrict__ out) {
    __shared__ float res[24*66];
    int c0 = blockIdx.x * 8;
    int tid = threadIdx.x;
    int w = tid >> 5, lane = tid & 31;
    int q = (w & 1)*32 + lane;
    int rg = w >> 1;                 // 0..3, rows rg*6 .. rg*6+5

    u64 acc[6];
    #pragma unroll
    for (int j = 0; j < 6; j++) acc[j] = 0ull;

    const float* qrow = g_qpn + (size_t)q*HID;
    #pragma unroll
    for (int ck = 0; ck < 8; ck++) {
        int k0 = ck*32;
        u64 qv[16];
        #pragma unroll
        for (int i = 0; i < 4; i++) {
            ulonglong2 p = *(const ulonglong2*)(qrow + k0 + i*8);
            ulonglong2 p2 = *(const ulonglong2*)(qrow + k0 + i*8 + 4);
            qv[i*4+0]=p.x; qv[i*4+1]=p.y; qv[i*4+2]=p2.x; qv[i*4+3]=p2.y;
        }
        #pragma unroll
        for (int j = 0; j < 6; j++) {
            int rowIdx = rg*6 + j;
            int gate = rowIdx >> 3, col = rowIdx & 7;
            const float* wr = qWih + (size_t)(gate*256 + c0 + col)*HID + k0;
            #pragma unroll
            for (int i = 0; i < 4; i++) {
                ulonglong2 p = *(const ulonglong2*)(wr + i*8);
                ulonglong2 p2 = *(const ulonglong2*)(wr + i*8 + 4);
                acc[j] = ffma2(qv[i*4+0], p.x, acc[j]);
                acc[j] = ffma2(qv[i*4+1], p.y, acc[j]);
                acc[j] = ffma2(qv[i*4+2], p2.x, acc[j]);
                acc[j] = ffma2(qv[i*4+3], p2.y, acc[j]);
            }
        }
    }
    #pragma unroll
    for (int j = 0; j < 6; j++)
        res[(rg*6 + j)*66 + q] = hsum2(acc[j]);
    __syncthreads();

    for (int o = tid; o < 512; o += 256) {
        int oq = o >> 3, col = o & 7;
        int c = c0 + col;
        float gr = res[(col)*66 + oq]      + qbih[c];
        float gz = res[(8+col)*66 + oq]    + qbih[256+c];
        float gn = res[(16+col)*66 + oq]   + qbih[512+c];
        float rv = 1.f/(1.f + expf(-(gr + qbhh[c])));
        float zv = 1.f/(1.f + expf(-(gz + qbhh[256+c])));
        float nv = tanhf(gn + rv*qbhh[512+c]);
        out[oq*256 + c] = (1.f - zv)*nv;
    }
}

// ---------------- launch ------------------------------------------------------
extern "C" void kernel_launch(void* const* d_in, const int* in_sizes, int n_in,
                              void* d_out, int out_size) {
    const int*   qt   = (const int*)d_in[0];
    const int*   pt   = (const int*)d_in[1];
    const int*   nt   = (const int*)d_in[2];
    const float* temb = (const float*)d_in[3];
    const float* tWih = (const float*)d_in[4];
    const float* tWhh = (const float*)d_in[5];
    const float* tbih = (const float*)d_in[6];
    const float* tbhh = (const float*)d_in[7];
    const float* demb = (const float*)d_in[8];
    const float* cWih = (const float*)d_in[9];
    const float* cWhh = (const float*)d_in[10];
    const float* cbih = (const float*)d_in[11];
    const float* cbhh = (const float*)d_in[12];
    const float* aWih = (const float*)d_in[13];
    const float* aWhh = (const float*)d_in[14];
    const float* abih = (const float*)d_in[15];
    const float* abhh = (const float*)d_in[16];
    const float* ptab = (const float*)d_in[17];
    const float* posW = (const float*)d_in[18];
    const float* posb = (const float*)d_in[19];
    const float* qWih = (const float*)d_in[20];
    const float* qbih = (const float*)d_in[22];
    const float* qbhh = (const float*)d_in[23];

    gi_gemm_k<<<120, 256>>>(qt, pt, nt, temb, demb,
                            tWih, tbih, cWih, cbih, aWih, abih);
    scan_k<<<128, 512>>>(tWhh, tbhh, cWhh, cbhh, aWhh, abhh);
    posdense_k<<<8, 256>>>(posW, posb, ptab);
    attend_k<<<QN, 256>>>();
    gemmgate_k<<<32, 256>>>(qWih, qbih, qbhh, (float*)d_out);
}